// round 11
// baseline (speedup 1.0000x reference)
#include <cuda_runtime.h>
#include <cuda_fp16.h>
#include <math.h>

#define BB 64
#define NN 10
#define ID 16
#define OD 16
#define IC 6912
#define JB 24          // j-tile for k_uhat (grid 288, 2 blocks/SM)
#define NTH 320        // k_uhat: warp = n; lane owns b = 2lane, 2lane+1
#define JT 16          // j's per k_xt block
#define RT_TH 256      // k_route: 16-lane groups, n = tid&15
#define RT_BLOCKS 592  // persistent: 148 SMs x 4
#define WSTG 6         // W ring stages (5 in flight)
#define UHAT_SMEM (61440 + 40960)  // W rings (10*6*1KB) + out staging

// Packed f32x2 helpers (sm_100+ PTX)
#define FFMA2(d, a, b) asm("fma.rn.f32x2 %0, %1, %2, %0;" : "+l"(d) : "l"(a), "l"(b))
#define FADD2(d, a)    asm("add.rn.f32x2 %0, %0, %1;"     : "+l"(d) : "l"(a))
// cp.async (LDGSTS)
#define CP16(dst, src) asm volatile("cp.async.ca.shared.global [%0], [%1], 16;" \
                                    :: "r"(dst), "l"(src))
#define CP_COMMIT()    asm volatile("cp.async.commit_group;")
#define CP_WAIT2()     asm volatile("cp.async.wait_group 2;")
#define CP_WAIT4()     asm volatile("cp.async.wait_group 4;")
// bulk shared->global store
#define BULK_ST(gdst, ssrc, bytes)                                             \
    asm volatile("cp.async.bulk.global.shared::cta.bulk_group [%0], [%1], %2;" \
                 :: "l"(gdst), "r"(ssrc), "r"(bytes) : "memory")
#define BULK_COMMIT()  asm volatile("cp.async.bulk.commit_group;")
#define BULK_WAIT_RD1() asm volatile("cp.async.bulk.wait_group.read 1;")
#define BULK_WAIT0()   asm volatile("cp.async.bulk.wait_group 0;")
#define FENCE_ASYNC()  asm volatile("fence.proxy.async.shared::cta;" ::: "memory")

// Scratch (device globals: allocation-free). u_hat fp16, layout [j][n][b][o].
__device__ __half g_uhat[(size_t)IC * NN * BB * OD];
__device__ __half g_xh[(size_t)IC * ID * BB];  // x fp16, [j][i][b]
__device__ float g_s0[BB * NN * OD];           // s from pass 0
__device__ float g_s1[BB * NN * OD];           // s from pass 1
__device__ float g_s2[BB * NN * OD];           // s from pass 2

// ───── Kernel T: x [b][j][i] fp32 -> g_xh [j][i][b] fp16; also zero g_s* ────
__global__ void k_xt(const float* __restrict__ x) {
    __shared__ __half th[ID][BB];
    const int tid = threadIdx.x;  // 256
    const int bid = blockIdx.x;
    if (bid < 30) {
        float* z = (bid < 10) ? g_s0 : (bid < 20) ? g_s1 : g_s2;
        int off = (bid % 10) * 1024;
#pragma unroll
        for (int r = 0; r < 4; r++) z[off + r * 256 + tid] = 0.f;
    }
    const int jb = bid * JT;
    for (int jj = 0; jj < JT; jj++) {
        const int j = jb + jj;
#pragma unroll
        for (int r = 0; r < 4; r++) {
            int e = r * 256 + tid;  // b = e>>4, i = e&15
            th[e & 15][e >> 4] =
                __float2half(x[((size_t)(e >> 4) * IC + j) * 16 + (e & 15)]);
        }
        __syncthreads();
#pragma unroll
        for (int r = 0; r < 2; r++) {
            int c = r * 256 + tid;          // u32 index: i = c>>5, b = (c&31)*2
            __half2 p = __halves2half2(th[c >> 5][(c & 31) * 2],
                                       th[c >> 5][(c & 31) * 2 + 1]);
            ((unsigned*)g_xh)[(size_t)j * 512 + c] = *(unsigned*)&p;
        }
        __syncthreads();
    }
}

// ───────────────────────────── Kernel A: u_hat GEMM ─────────────────────────
// W: per-warp 6-stage CP16 ring (5 stages / 2.5 KB per warp in flight -> 50 KB
// per SM outstanding: 2x the BW*latency product). x: fp16 coalesced LDG.
// OUT: staged in smem, one 2KB cp.async.bulk per (j, n).
__global__ __launch_bounds__(NTH, 2) void k_uhat(const float* __restrict__ W) {
    extern __shared__ __align__(16) char dsm[];
    float* wsf = (float*)dsm;            // [10 warps][6 stages][256 f] = 61440B
    char* outs = dsm + 61440;            // [2 slots][10 n][2048B]      = 40960B
    const int tid = threadIdx.x;
    const int w = tid >> 5;       // warp = n
    const int lane = tid & 31;
    const int j0 = blockIdx.x * JB;

    const float* wsrc = W + (size_t)w * IC * 256;
    const unsigned wb_sh = (unsigned)__cvta_generic_to_shared(wsf + w * (WSTG * 256));
    const unsigned d1 = wb_sh + lane * 16;
    const unsigned d2 = wb_sh + 512 + lane * 16;

#define WISSUE(jv, sv)                                   \
    do {                                                 \
        const float* s_ = wsrc + (size_t)(jv) * 256;     \
        CP16(d1 + (sv) * 1024, s_ + lane * 4);           \
        CP16(d2 + (sv) * 1024, s_ + lane * 4 + 128);     \
    } while (0)

#pragma unroll
    for (int s = 0; s < WSTG - 1; s++) { WISSUE(j0 + s, s); CP_COMMIT(); }

    const unsigned outsh_base = (unsigned)__cvta_generic_to_shared(outs) +
                                w * 2048 + lane * 64;

    unsigned long long s2a[8], s2b[8];
#pragma unroll
    for (int k = 0; k < 8; k++) { s2a[k] = 0ull; s2b[k] = 0ull; }

    int slot = 0, rslot = WSTG - 1;  // consume slot, refill slot
    for (int jj = 0; jj < JB; jj++) {
        const int j = j0 + jj;
        const unsigned* xp = (const unsigned*)g_xh + (size_t)j * 512;
        unsigned x32[16];
#pragma unroll
        for (int i = 0; i < ID; i++) x32[i] = xp[i * 32 + lane];

        CP_WAIT4();   // <=4 groups pending -> stage `slot` landed
        __syncwarp();

        const ulonglong2* wb = (const ulonglong2*)(wsf + (w * WSTG + slot) * 256);

        unsigned long long u2a[8], u2b[8];
#pragma unroll
        for (int k = 0; k < 8; k++) { u2a[k] = 0ull; u2b[k] = 0ull; }
#pragma unroll
        for (int i = 0; i < ID; i++) {
            float2 fx = __half22float2(*(__half2*)&x32[i]);  // b=2lane, 2lane+1
            unsigned long long xa2, xb2;
            asm("mov.b64 %0, {%1, %1};" : "=l"(xa2) : "f"(fx.x));
            asm("mov.b64 %0, {%1, %1};" : "=l"(xb2) : "f"(fx.y));
            ulonglong2 p0 = wb[i * 4 + 0], p1 = wb[i * 4 + 1];
            ulonglong2 p2 = wb[i * 4 + 2], p3 = wb[i * 4 + 3];
            FFMA2(u2a[0], xa2, p0.x); FFMA2(u2a[1], xa2, p0.y);
            FFMA2(u2a[2], xa2, p1.x); FFMA2(u2a[3], xa2, p1.y);
            FFMA2(u2a[4], xa2, p2.x); FFMA2(u2a[5], xa2, p2.y);
            FFMA2(u2a[6], xa2, p3.x); FFMA2(u2a[7], xa2, p3.y);
            FFMA2(u2b[0], xb2, p0.x); FFMA2(u2b[1], xb2, p0.y);
            FFMA2(u2b[2], xb2, p1.x); FFMA2(u2b[3], xb2, p1.y);
            FFMA2(u2b[4], xb2, p2.x); FFMA2(u2b[5], xb2, p2.y);
            FFMA2(u2b[6], xb2, p3.x); FFMA2(u2b[7], xb2, p3.y);
        }

        {
            __align__(16) __half2 ha[8], hb[8];
#pragma unroll
            for (int k = 0; k < 8; k++) {
                float lo, hi;
                asm("mov.b64 {%0, %1}, %2;" : "=f"(lo), "=f"(hi) : "l"(u2a[k]));
                ha[k] = __floats2half2_rn(lo, hi);
                asm("mov.b64 {%0, %1}, %2;" : "=f"(lo), "=f"(hi) : "l"(u2b[k]));
                hb[k] = __floats2half2_rn(lo, hi);
            }
            if (lane == 0) BULK_WAIT_RD1();
            __syncwarp();
            const unsigned ob = outsh_base + (jj & 1) * 20480;
            asm volatile("st.shared.v4.b32 [%0], {%1,%2,%3,%4};" :: "r"(ob),
                "r"(*(unsigned*)&ha[0]), "r"(*(unsigned*)&ha[1]),
                "r"(*(unsigned*)&ha[2]), "r"(*(unsigned*)&ha[3]));
            asm volatile("st.shared.v4.b32 [%0], {%1,%2,%3,%4};" :: "r"(ob + 16),
                "r"(*(unsigned*)&ha[4]), "r"(*(unsigned*)&ha[5]),
                "r"(*(unsigned*)&ha[6]), "r"(*(unsigned*)&ha[7]));
            asm volatile("st.shared.v4.b32 [%0], {%1,%2,%3,%4};" :: "r"(ob + 32),
                "r"(*(unsigned*)&hb[0]), "r"(*(unsigned*)&hb[1]),
                "r"(*(unsigned*)&hb[2]), "r"(*(unsigned*)&hb[3]));
            asm volatile("st.shared.v4.b32 [%0], {%1,%2,%3,%4};" :: "r"(ob + 48),
                "r"(*(unsigned*)&hb[4]), "r"(*(unsigned*)&hb[5]),
                "r"(*(unsigned*)&hb[6]), "r"(*(unsigned*)&hb[7]));
            __syncwarp();
            if (lane == 0) {
                FENCE_ASYNC();
                const char* gdst = (const char*)g_uhat + ((size_t)j * NN + w) * 2048;
                unsigned ssrc = (unsigned)__cvta_generic_to_shared(outs) +
                                (jj & 1) * 20480 + w * 2048;
                BULK_ST(gdst, ssrc, 2048);
                BULK_COMMIT();
            }
#pragma unroll
            for (int k = 0; k < 8; k++) { FADD2(s2a[k], u2a[k]); FADD2(s2b[k], u2b[k]); }
        }

        if (jj + WSTG - 1 < JB) WISSUE(j0 + jj + WSTG - 1, rslot);
        CP_COMMIT();
        if (++slot == WSTG) slot = 0;
        if (++rslot == WSTG) rslot = 0;
    }
#undef WISSUE
    if (lane == 0) BULK_WAIT0();

    const int b0 = 2 * lane;
    float* spa = g_s0 + (b0 * NN + w) * OD;
    float* spb = g_s0 + ((b0 + 1) * NN + w) * OD;
#pragma unroll
    for (int k = 0; k < 8; k++) {
        float lo, hi;
        asm("mov.b64 {%0, %1}, %2;" : "=f"(lo), "=f"(hi) : "l"(s2a[k]));
        atomicAdd(spa + 2 * k, 0.1f * lo);
        atomicAdd(spa + 2 * k + 1, 0.1f * hi);
        asm("mov.b64 {%0, %1}, %2;" : "=f"(lo), "=f"(hi) : "l"(s2b[k]));
        atomicAdd(spb + 2 * k, 0.1f * lo);
        atomicAdd(spb + 2 * k + 1, 0.1f * hi);
    }
}

// squash scale for one 16-float s vector
__device__ __forceinline__ float squash_scale(const float* s) {
    float s2 = 0.f;
#pragma unroll
    for (int o = 0; o < OD; o++) s2 = fmaf(s[o], s[o], s2);
    return (s2 / (1.f + s2)) * rsqrtf(s2 + 1e-7f);
}

// ───────────────────── Kernel C: PERSISTENT routing pass ────────────────────
// occ 4 (32 warps/SM): grid 592 = 148 x 4, regs forced <=64. 2-j super-stages,
// interleaved shfl chains, 3 supers (31.5 KB) in flight.
__global__ __launch_bounds__(RT_TH, 4) void k_route(int pass) {
    __shared__ __align__(16) char tile[8][5376];  // per j: 16 b x 336 B (pad)
    const int tid = threadIdx.x;
    const int n = tid & 15;
    const int bg = tid >> 4;
    const int bgrp = blockIdx.x & 3;
    const int idx = blockIdx.x >> 2;                   // 0..147
    const int pbeg = (idx * (IC / 2)) / 148;
    const int pend = ((idx + 1) * (IC / 2)) / 148;
    const int nsup = pend - pbeg;                      // 23..24 supers
    const int jbeg = 2 * pbeg;
    const int b = bgrp * 16 + bg;
    const bool act = (n < NN);

    // copy plan: 320 x 16B chunks/j; layout [j][n][b][o] -> 2048B per (j,n)
    const int c0 = tid, c1 = tid + 256;
    const bool has1 = (c1 < 320);
    const unsigned tb = (unsigned)__cvta_generic_to_shared(&tile[0][0]);
    const int n0 = c0 >> 5, t0 = c0 & 31, bg0 = t0 >> 1, hf0 = t0 & 1;
    const int n1 = c1 >> 5, t1 = c1 & 31, bg1 = t1 >> 1, hf1 = t1 & 1;
    const unsigned dst0 = tb + bg0 * 336 + n0 * 32 + hf0 * 16;
    const unsigned dst1 = tb + bg1 * 336 + n1 * 32 + hf1 * 16;
    const size_t so0 = (size_t)n0 * 2048 + (bgrp * 16 + bg0) * 32 + hf0 * 16;
    const size_t so1 = (size_t)n1 * 2048 + (bgrp * 16 + bg1) * 32 + hf1 * 16;
    const char* gu = (const char*)g_uhat;

#define RISSUE(jv, sl)                                                       \
    do {                                                                     \
        CP16(dst0 + (sl) * 5376, gu + (size_t)(jv) * 20480 + so0);           \
        if (has1) CP16(dst1 + (sl) * 5376, gu + (size_t)(jv) * 20480 + so1); \
    } while (0)

#pragma unroll
    for (int sp = 0; sp < 3; sp++) {
        if (sp < nsup) { RISSUE(jbeg + 2 * sp, 2 * sp); RISSUE(jbeg + 2 * sp + 1, 2 * sp + 1); }
        CP_COMMIT();
    }

    // fused squash prologue -> vs (fp16 pairs)
    __half2 vs2[8];
    {
        const int row = (b * NN + (act ? n : 0)) * OD;
        float vsf[OD];
        {
            const float4* p0 = (const float4*)(g_s0 + row);
            float sv[OD];
#pragma unroll
            for (int k = 0; k < 4; k++) {
                float4 v = p0[k];
                sv[4 * k] = v.x; sv[4 * k + 1] = v.y;
                sv[4 * k + 2] = v.z; sv[4 * k + 3] = v.w;
            }
            float sc = squash_scale(sv);
#pragma unroll
            for (int o = 0; o < OD; o++) vsf[o] = sc * sv[o];
        }
        if (pass == 2) {
            const float4* p1 = (const float4*)(g_s1 + row);
            float sv[OD];
#pragma unroll
            for (int k = 0; k < 4; k++) {
                float4 v = p1[k];
                sv[4 * k] = v.x; sv[4 * k + 1] = v.y;
                sv[4 * k + 2] = v.z; sv[4 * k + 3] = v.w;
            }
            float sc = squash_scale(sv);
#pragma unroll
            for (int o = 0; o < OD; o++) vsf[o] = fmaf(sc, sv[o], vsf[o]);
        }
#pragma unroll
        for (int k = 0; k < 8; k++)
            vs2[k] = __floats2half2_rn(vsf[2 * k], vsf[2 * k + 1]);
    }

    float s_acc[OD];
#pragma unroll
    for (int o = 0; o < OD; o++) s_acc[o] = 0.f;

    const int nl = act ? n : 0;
    for (int k = 0; k < nsup; k++) {
        CP_WAIT2();        // super k landed
        __syncthreads();   // visible to all; prior super's reads done

        const int s = (2 * k) & 7;  // even slot; pair = s, s+1 (no wrap)
        const char* tp0 = tile[s] + bg * 336 + nl * 32;
        const char* tp1 = tile[s + 1] + bg * 336 + nl * 32;
        uint4 cA0 = *(const uint4*)tp0;
        uint4 cB0 = *(const uint4*)(tp0 + 16);
        uint4 cA1 = *(const uint4*)tp1;
        uint4 cB1 = *(const uint4*)(tp1 + 16);
        const __half2* hA0 = (const __half2*)&cA0;
        const __half2* hB0 = (const __half2*)&cB0;
        const __half2* hA1 = (const __half2*)&cA1;
        const __half2* hB1 = (const __half2*)&cB1;

        __half2 dA0 = __hmul2(hA0[0], vs2[0]), dB0 = __hmul2(hB0[0], vs2[4]);
        __half2 dA1 = __hmul2(hA1[0], vs2[0]), dB1 = __hmul2(hB1[0], vs2[4]);
#pragma unroll
        for (int q = 1; q < 4; q++) {
            dA0 = __hfma2(hA0[q], vs2[q], dA0); dB0 = __hfma2(hB0[q], vs2[4 + q], dB0);
            dA1 = __hfma2(hA1[q], vs2[q], dA1); dB1 = __hfma2(hB1[q], vs2[4 + q], dB1);
        }
        __half2 ds0 = __hadd2(dA0, dB0), ds1 = __hadd2(dA1, dB1);
        float d0 = __low2float(ds0) + __high2float(ds0);
        float d1 = __low2float(ds1) + __high2float(ds1);

        float e0 = act ? __expf(d0) : 0.f;
        float e1 = act ? __expf(d1) : 0.f;
        float s0 = e0, s1 = e1;
#pragma unroll
        for (int m = 1; m < 16; m <<= 1) {  // interleaved chains
            s0 += __shfl_xor_sync(0xFFFFFFFFu, s0, m, 16);
            s1 += __shfl_xor_sync(0xFFFFFFFFu, s1, m, 16);
        }
        float c0 = __fdividef(e0, s0);
        float c1 = __fdividef(e1, s1);

#pragma unroll
        for (int q = 0; q < 4; q++) {
            float2 f = __half22float2(hA0[q]);
            s_acc[2 * q] = fmaf(c0, f.x, s_acc[2 * q]);
            s_acc[2 * q + 1] = fmaf(c0, f.y, s_acc[2 * q + 1]);
            f = __half22float2(hB0[q]);
            s_acc[8 + 2 * q] = fmaf(c0, f.x, s_acc[8 + 2 * q]);
            s_acc[9 + 2 * q] = fmaf(c0, f.y, s_acc[9 + 2 * q]);
            f = __half22float2(hA1[q]);
            s_acc[2 * q] = fmaf(c1, f.x, s_acc[2 * q]);
            s_acc[2 * q + 1] = fmaf(c1, f.y, s_acc[2 * q + 1]);
            f = __half22float2(hB1[q]);
            s_acc[8 + 2 * q] = fmaf(c1, f.x, s_acc[8 + 2 * q]);
            s_acc[9 + 2 * q] = fmaf(c1, f.y, s_acc[9 + 2 * q]);
        }

        const int kn = k + 3;
        if (kn < nsup) {
            const int sn = (2 * kn) & 7;
            RISSUE(jbeg + 2 * kn, sn);
            RISSUE(jbeg + 2 * kn + 1, sn + 1);
        }
        CP_COMMIT();
    }
#undef RISSUE

    if (act) {
        float* sp = ((pass == 1) ? g_s1 : g_s2) + (b * NN + n) * OD;
#pragma unroll
        for (int o = 0; o < OD; o++) atomicAdd(sp + o, s_acc[o]);
    }
}

// ─────────────────── Final: v2 = squash(s2) -> output ───────────────────────
__global__ void k_squash_out(float* __restrict__ out) {
    int t = threadIdx.x;
    if (t >= BB * NN) return;
    const float4* sp = (const float4*)(g_s2 + t * OD);
    float4 a = sp[0], b4 = sp[1], c4 = sp[2], d4 = sp[3];
    float s[OD] = {a.x, a.y, a.z, a.w, b4.x, b4.y, b4.z, b4.w,
                   c4.x, c4.y, c4.z, c4.w, d4.x, d4.y, d4.z, d4.w};
    float sc = squash_scale(s);
    float4* op = (float4*)(out + t * OD);
    op[0] = make_float4(sc * s[0], sc * s[1], sc * s[2], sc * s[3]);
    op[1] = make_float4(sc * s[4], sc * s[5], sc * s[6], sc * s[7]);
    op[2] = make_float4(sc * s[8], sc * s[9], sc * s[10], sc * s[11]);
    op[3] = make_float4(sc * s[12], sc * s[13], sc * s[14], sc * s[15]);
}

extern "C" void kernel_launch(void* const* d_in, const int* in_sizes, int n_in,
                              void* d_out, int out_size) {
    const float* x = (const float*)d_in[0];  // [64, 6912, 16]
    const float* W = (const float*)d_in[1];  // [10, 6912, 16, 16]
    float* out = (float*)d_out;              // [64, 10, 16]

    cudaFuncSetAttribute(k_uhat, cudaFuncAttributeMaxDynamicSharedMemorySize,
                         UHAT_SMEM);

    k_xt<<<IC / JT, 256>>>(x);               // x -> fp16 [j][i][b]; zero s bufs
    k_uhat<<<IC / JB, NTH, UHAT_SMEM>>>(W);  // u_hat (fp16) + fused s0
    k_route<<<RT_BLOCKS, RT_TH>>>(1);        // squash(s0); emit s1
    k_route<<<RT_BLOCKS, RT_TH>>>(2);        // squash(s0)+squash(s1); emit s2
    k_squash_out<<<1, 640>>>(out);           // v2 -> output
}

// round 12
// speedup vs baseline: 1.0613x; 1.0613x over previous
#include <cuda_runtime.h>
#include <cuda_fp16.h>
#include <math.h>

#define BB 64
#define NN 10
#define ID 16
#define OD 16
#define IC 6912
#define JB 24          // j-tile for k_uhat (grid 288, 2 blocks/SM)
#define NTH 320        // k_uhat: warp = n; lane owns b = 2lane, 2lane+1
#define JT 16          // j's per k_xt block
#define RT_TH 256      // k_route: 16-lane groups, n = tid&15
#define RT_BLOCKS 444  // persistent: 111 x 4 (3 blocks/SM)
#define NTRIP (IC / 3) // 2304 j-triples
#define UHAT_SMEM (40960 + 40960)  // W rings + out staging

// Packed f32x2 helpers (sm_100+ PTX)
#define FFMA2(d, a, b) asm("fma.rn.f32x2 %0, %1, %2, %0;" : "+l"(d) : "l"(a), "l"(b))
#define FADD2(d, a)    asm("add.rn.f32x2 %0, %0, %1;"     : "+l"(d) : "l"(a))
// cp.async (LDGSTS)
#define CP16(dst, src) asm volatile("cp.async.ca.shared.global [%0], [%1], 16;" \
                                    :: "r"(dst), "l"(src))
#define CP_COMMIT()    asm volatile("cp.async.commit_group;")
#define CP_WAIT2()     asm volatile("cp.async.wait_group 2;")
// bulk shared->global store
#define BULK_ST(gdst, ssrc, bytes)                                             \
    asm volatile("cp.async.bulk.global.shared::cta.bulk_group [%0], [%1], %2;" \
                 :: "l"(gdst), "r"(ssrc), "r"(bytes) : "memory")
#define BULK_COMMIT()  asm volatile("cp.async.bulk.commit_group;")
#define BULK_WAIT_RD1() asm volatile("cp.async.bulk.wait_group.read 1;")
#define BULK_WAIT0()   asm volatile("cp.async.bulk.wait_group 0;")
#define FENCE_ASYNC()  asm volatile("fence.proxy.async.shared::cta;" ::: "memory")

// Scratch (device globals: allocation-free). u_hat fp16, layout [j][n][b][o].
__device__ __half g_uhat[(size_t)IC * NN * BB * OD];
__device__ __half g_xh[(size_t)IC * ID * BB];  // x fp16, [j][i][b]
__device__ float g_s0[BB * NN * OD];           // s from pass 0
__device__ float g_s1[BB * NN * OD];           // s from pass 1
__device__ float g_s2[BB * NN * OD];           // s from pass 2

// ───── Kernel T: x [b][j][i] fp32 -> g_xh [j][i][b] fp16; also zero g_s* ────
__global__ void k_xt(const float* __restrict__ x) {
    __shared__ __half th[ID][BB];
    const int tid = threadIdx.x;  // 256
    const int bid = blockIdx.x;
    if (bid < 30) {
        float* z = (bid < 10) ? g_s0 : (bid < 20) ? g_s1 : g_s2;
        int off = (bid % 10) * 1024;
#pragma unroll
        for (int r = 0; r < 4; r++) z[off + r * 256 + tid] = 0.f;
    }
    const int jb = bid * JT;
    for (int jj = 0; jj < JT; jj++) {
        const int j = jb + jj;
#pragma unroll
        for (int r = 0; r < 4; r++) {
            int e = r * 256 + tid;  // b = e>>4, i = e&15
            th[e & 15][e >> 4] =
                __float2half(x[((size_t)(e >> 4) * IC + j) * 16 + (e & 15)]);
        }
        __syncthreads();
#pragma unroll
        for (int r = 0; r < 2; r++) {
            int c = r * 256 + tid;          // u32 index: i = c>>5, b = (c&31)*2
            __half2 p = __halves2half2(th[c >> 5][(c & 31) * 2],
                                       th[c >> 5][(c & 31) * 2 + 1]);
            ((unsigned*)g_xh)[(size_t)j * 512 + c] = *(unsigned*)&p;
        }
        __syncthreads();
    }
}

// ───────────────────────────── Kernel A: u_hat GEMM ─────────────────────────
// W: per-warp 4-stage CP16 ring (warp-local syncs only). x: fp16 coalesced
// LDG. OUT: staged in smem, one 2KB cp.async.bulk per (j, n).  (R10 config)
__global__ __launch_bounds__(NTH, 2) void k_uhat(const float* __restrict__ W) {
    extern __shared__ __align__(16) char dsm[];
    float* wsf = (float*)dsm;            // [10 warps][4 stages][256 f] = 40960B
    char* outs = dsm + 40960;            // [2 slots][10 n][2048B]      = 40960B
    const int tid = threadIdx.x;
    const int w = tid >> 5;       // warp = n
    const int lane = tid & 31;
    const int j0 = blockIdx.x * JB;

    const float* wsrc = W + (size_t)w * IC * 256;
    const unsigned wb_sh = (unsigned)__cvta_generic_to_shared(wsf + w * 1024);
    const unsigned d1 = wb_sh + lane * 16;
    const unsigned d2 = wb_sh + 512 + lane * 16;

#define WISSUE(jv, sv)                                   \
    do {                                                 \
        const float* s_ = wsrc + (size_t)(jv) * 256;     \
        CP16(d1 + (sv) * 1024, s_ + lane * 4);           \
        CP16(d2 + (sv) * 1024, s_ + lane * 4 + 128);     \
    } while (0)

#pragma unroll
    for (int s = 0; s < 3; s++) { WISSUE(j0 + s, s); CP_COMMIT(); }

    const unsigned outsh_base = (unsigned)__cvta_generic_to_shared(outs) +
                                w * 2048 + lane * 64;

    unsigned long long s2a[8], s2b[8];
#pragma unroll
    for (int k = 0; k < 8; k++) { s2a[k] = 0ull; s2b[k] = 0ull; }

    for (int jj = 0; jj < JB; jj++) {
        const int j = j0 + jj;
        const unsigned* xp = (const unsigned*)g_xh + (size_t)j * 512;
        unsigned x32[16];
#pragma unroll
        for (int i = 0; i < ID; i++) x32[i] = xp[i * 32 + lane];

        CP_WAIT2();
        __syncwarp();

        const ulonglong2* wb = (const ulonglong2*)(wsf + (w * 4 + (jj & 3)) * 256);

        unsigned long long u2a[8], u2b[8];
#pragma unroll
        for (int k = 0; k < 8; k++) { u2a[k] = 0ull; u2b[k] = 0ull; }
#pragma unroll
        for (int i = 0; i < ID; i++) {
            float2 fx = __half22float2(*(__half2*)&x32[i]);  // b=2lane, 2lane+1
            unsigned long long xa2, xb2;
            asm("mov.b64 %0, {%1, %1};" : "=l"(xa2) : "f"(fx.x));
            asm("mov.b64 %0, {%1, %1};" : "=l"(xb2) : "f"(fx.y));
            ulonglong2 p0 = wb[i * 4 + 0], p1 = wb[i * 4 + 1];
            ulonglong2 p2 = wb[i * 4 + 2], p3 = wb[i * 4 + 3];
            FFMA2(u2a[0], xa2, p0.x); FFMA2(u2a[1], xa2, p0.y);
            FFMA2(u2a[2], xa2, p1.x); FFMA2(u2a[3], xa2, p1.y);
            FFMA2(u2a[4], xa2, p2.x); FFMA2(u2a[5], xa2, p2.y);
            FFMA2(u2a[6], xa2, p3.x); FFMA2(u2a[7], xa2, p3.y);
            FFMA2(u2b[0], xb2, p0.x); FFMA2(u2b[1], xb2, p0.y);
            FFMA2(u2b[2], xb2, p1.x); FFMA2(u2b[3], xb2, p1.y);
            FFMA2(u2b[4], xb2, p2.x); FFMA2(u2b[5], xb2, p2.y);
            FFMA2(u2b[6], xb2, p3.x); FFMA2(u2b[7], xb2, p3.y);
        }

        {
            __align__(16) __half2 ha[8], hb[8];
#pragma unroll
            for (int k = 0; k < 8; k++) {
                float lo, hi;
                asm("mov.b64 {%0, %1}, %2;" : "=f"(lo), "=f"(hi) : "l"(u2a[k]));
                ha[k] = __floats2half2_rn(lo, hi);
                asm("mov.b64 {%0, %1}, %2;" : "=f"(lo), "=f"(hi) : "l"(u2b[k]));
                hb[k] = __floats2half2_rn(lo, hi);
            }
            if (lane == 0) BULK_WAIT_RD1();
            __syncwarp();
            const unsigned ob = outsh_base + (jj & 1) * 20480;
            asm volatile("st.shared.v4.b32 [%0], {%1,%2,%3,%4};" :: "r"(ob),
                "r"(*(unsigned*)&ha[0]), "r"(*(unsigned*)&ha[1]),
                "r"(*(unsigned*)&ha[2]), "r"(*(unsigned*)&ha[3]));
            asm volatile("st.shared.v4.b32 [%0], {%1,%2,%3,%4};" :: "r"(ob + 16),
                "r"(*(unsigned*)&ha[4]), "r"(*(unsigned*)&ha[5]),
                "r"(*(unsigned*)&ha[6]), "r"(*(unsigned*)&ha[7]));
            asm volatile("st.shared.v4.b32 [%0], {%1,%2,%3,%4};" :: "r"(ob + 32),
                "r"(*(unsigned*)&hb[0]), "r"(*(unsigned*)&hb[1]),
                "r"(*(unsigned*)&hb[2]), "r"(*(unsigned*)&hb[3]));
            asm volatile("st.shared.v4.b32 [%0], {%1,%2,%3,%4};" :: "r"(ob + 48),
                "r"(*(unsigned*)&hb[4]), "r"(*(unsigned*)&hb[5]),
                "r"(*(unsigned*)&hb[6]), "r"(*(unsigned*)&hb[7]));
            __syncwarp();
            if (lane == 0) {
                FENCE_ASYNC();
                const char* gdst = (const char*)g_uhat + ((size_t)j * NN + w) * 2048;
                unsigned ssrc = (unsigned)__cvta_generic_to_shared(outs) +
                                (jj & 1) * 20480 + w * 2048;
                BULK_ST(gdst, ssrc, 2048);
                BULK_COMMIT();
            }
#pragma unroll
            for (int k = 0; k < 8; k++) { FADD2(s2a[k], u2a[k]); FADD2(s2b[k], u2b[k]); }
        }

        if (jj + 3 < JB) WISSUE(j0 + jj + 3, (jj + 3) & 3);
        CP_COMMIT();
    }
#undef WISSUE
    if (lane == 0) BULK_WAIT0();

    const int b0 = 2 * lane;
    float* spa = g_s0 + (b0 * NN + w) * OD;
    float* spb = g_s0 + ((b0 + 1) * NN + w) * OD;
#pragma unroll
    for (int k = 0; k < 8; k++) {
        float lo, hi;
        asm("mov.b64 {%0, %1}, %2;" : "=f"(lo), "=f"(hi) : "l"(s2a[k]));
        atomicAdd(spa + 2 * k, 0.1f * lo);
        atomicAdd(spa + 2 * k + 1, 0.1f * hi);
        asm("mov.b64 {%0, %1}, %2;" : "=f"(lo), "=f"(hi) : "l"(s2b[k]));
        atomicAdd(spb + 2 * k, 0.1f * lo);
        atomicAdd(spb + 2 * k + 1, 0.1f * hi);
    }
}

// squash scale for one 16-float s vector
__device__ __forceinline__ float squash_scale(const float* s) {
    float s2 = 0.f;
#pragma unroll
    for (int o = 0; o < OD; o++) s2 = fmaf(s[o], s[o], s2);
    return (s2 / (1.f + s2)) * rsqrtf(s2 + 1e-7f);
}

// ───────────────────── Kernel C: PERSISTENT routing pass ────────────────────
// 3-j SUPER-STAGES: one CP_WAIT + __syncthreads per 3 j's; three interleaved
// shfl softmax chains. Ring = 9 j-slots (aligned triples, no wrap); 3 supers
// (47 KB) in flight. occ 3 (regs free to 85).
__global__ __launch_bounds__(RT_TH, 3) void k_route(int pass) {
    __shared__ __align__(16) char tile[9][5376];  // per j: 16 b x 336 B (pad)
    const int tid = threadIdx.x;
    const int n = tid & 15;
    const int bg = tid >> 4;
    const int bgrp = blockIdx.x & 3;
    const int idx = blockIdx.x >> 2;                   // 0..110
    const int tbeg = (idx * NTRIP) / 111;
    const int tend = ((idx + 1) * NTRIP) / 111;
    const int nsup = tend - tbeg;                      // 20..21 supers (3 j each)
    const int jbeg = 3 * tbeg;
    const int b = bgrp * 16 + bg;
    const bool act = (n < NN);

    // copy plan: 320 x 16B chunks/j; layout [j][n][b][o] -> 2048B per (j,n)
    const int c0 = tid, c1 = tid + 256;
    const bool has1 = (c1 < 320);
    const unsigned tb = (unsigned)__cvta_generic_to_shared(&tile[0][0]);
    const int n0 = c0 >> 5, t0 = c0 & 31, bg0 = t0 >> 1, hf0 = t0 & 1;
    const int n1 = c1 >> 5, t1 = c1 & 31, bg1 = t1 >> 1, hf1 = t1 & 1;
    const unsigned dst0 = tb + bg0 * 336 + n0 * 32 + hf0 * 16;
    const unsigned dst1 = tb + bg1 * 336 + n1 * 32 + hf1 * 16;
    const size_t so0 = (size_t)n0 * 2048 + (bgrp * 16 + bg0) * 32 + hf0 * 16;
    const size_t so1 = (size_t)n1 * 2048 + (bgrp * 16 + bg1) * 32 + hf1 * 16;
    const char* gu = (const char*)g_uhat;

#define RISSUE(jv, sl)                                                       \
    do {                                                                     \
        CP16(dst0 + (sl) * 5376, gu + (size_t)(jv) * 20480 + so0);           \
        if (has1) CP16(dst1 + (sl) * 5376, gu + (size_t)(jv) * 20480 + so1); \
    } while (0)

#pragma unroll
    for (int sp = 0; sp < 3; sp++) {  // 3 super-stages in flight
        if (sp < nsup) {
            RISSUE(jbeg + 3 * sp, 3 * sp);
            RISSUE(jbeg + 3 * sp + 1, 3 * sp + 1);
            RISSUE(jbeg + 3 * sp + 2, 3 * sp + 2);
        }
        CP_COMMIT();
    }

    // fused squash prologue -> vs (fp16 pairs)
    __half2 vs2[8];
    {
        const int row = (b * NN + (act ? n : 0)) * OD;
        float vsf[OD];
        {
            const float4* p0 = (const float4*)(g_s0 + row);
            float sv[OD];
#pragma unroll
            for (int k = 0; k < 4; k++) {
                float4 v = p0[k];
                sv[4 * k] = v.x; sv[4 * k + 1] = v.y;
                sv[4 * k + 2] = v.z; sv[4 * k + 3] = v.w;
            }
            float sc = squash_scale(sv);
#pragma unroll
            for (int o = 0; o < OD; o++) vsf[o] = sc * sv[o];
        }
        if (pass == 2) {
            const float4* p1 = (const float4*)(g_s1 + row);
            float sv[OD];
#pragma unroll
            for (int k = 0; k < 4; k++) {
                float4 v = p1[k];
                sv[4 * k] = v.x; sv[4 * k + 1] = v.y;
                sv[4 * k + 2] = v.z; sv[4 * k + 3] = v.w;
            }
            float sc = squash_scale(sv);
#pragma unroll
            for (int o = 0; o < OD; o++) vsf[o] = fmaf(sc, sv[o], vsf[o]);
        }
#pragma unroll
        for (int k = 0; k < 8; k++)
            vs2[k] = __floats2half2_rn(vsf[2 * k], vsf[2 * k + 1]);
    }

    float s_acc[OD];
#pragma unroll
    for (int o = 0; o < OD; o++) s_acc[o] = 0.f;

    const int nl = act ? n : 0;
    int s = 0;  // slot of first j of current super (0,3,6 cycle)
    for (int k = 0; k < nsup; k++) {
        CP_WAIT2();        // super k landed
        __syncthreads();   // visible to all; super k-3's readers done

        const char* tp0 = tile[s] + bg * 336 + nl * 32;
        const char* tp1 = tile[s + 1] + bg * 336 + nl * 32;
        const char* tp2 = tile[s + 2] + bg * 336 + nl * 32;
        uint4 cA0 = *(const uint4*)tp0, cB0 = *(const uint4*)(tp0 + 16);
        uint4 cA1 = *(const uint4*)tp1, cB1 = *(const uint4*)(tp1 + 16);
        uint4 cA2 = *(const uint4*)tp2, cB2 = *(const uint4*)(tp2 + 16);
        const __half2* hA0 = (const __half2*)&cA0;
        const __half2* hB0 = (const __half2*)&cB0;
        const __half2* hA1 = (const __half2*)&cA1;
        const __half2* hB1 = (const __half2*)&cB1;
        const __half2* hA2 = (const __half2*)&cA2;
        const __half2* hB2 = (const __half2*)&cB2;

        __half2 dA0 = __hmul2(hA0[0], vs2[0]), dB0 = __hmul2(hB0[0], vs2[4]);
        __half2 dA1 = __hmul2(hA1[0], vs2[0]), dB1 = __hmul2(hB1[0], vs2[4]);
        __half2 dA2 = __hmul2(hA2[0], vs2[0]), dB2 = __hmul2(hB2[0], vs2[4]);
#pragma unroll
        for (int q = 1; q < 4; q++) {
            dA0 = __hfma2(hA0[q], vs2[q], dA0); dB0 = __hfma2(hB0[q], vs2[4 + q], dB0);
            dA1 = __hfma2(hA1[q], vs2[q], dA1); dB1 = __hfma2(hB1[q], vs2[4 + q], dB1);
            dA2 = __hfma2(hA2[q], vs2[q], dA2); dB2 = __hfma2(hB2[q], vs2[4 + q], dB2);
        }
        __half2 ds0 = __hadd2(dA0, dB0), ds1 = __hadd2(dA1, dB1), ds2 = __hadd2(dA2, dB2);
        float d0 = __low2float(ds0) + __high2float(ds0);
        float d1 = __low2float(ds1) + __high2float(ds1);
        float d2 = __low2float(ds2) + __high2float(ds2);

        float e0 = act ? __expf(d0) : 0.f;
        float e1 = act ? __expf(d1) : 0.f;
        float e2 = act ? __expf(d2) : 0.f;
        float s0 = e0, s1 = e1, s2 = e2;
#pragma unroll
        for (int m = 1; m < 16; m <<= 1) {  // interleaved chains
            s0 += __shfl_xor_sync(0xFFFFFFFFu, s0, m, 16);
            s1 += __shfl_xor_sync(0xFFFFFFFFu, s1, m, 16);
            s2 += __shfl_xor_sync(0xFFFFFFFFu, s2, m, 16);
        }
        float c0 = __fdividef(e0, s0);
        float c1 = __fdividef(e1, s1);
        float c2 = __fdividef(e2, s2);

#pragma unroll
        for (int q = 0; q < 4; q++) {
            float2 f = __half22float2(hA0[q]);
            s_acc[2 * q] = fmaf(c0, f.x, s_acc[2 * q]);
            s_acc[2 * q + 1] = fmaf(c0, f.y, s_acc[2 * q + 1]);
            f = __half22float2(hB0[q]);
            s_acc[8 + 2 * q] = fmaf(c0, f.x, s_acc[8 + 2 * q]);
            s_acc[9 + 2 * q] = fmaf(c0, f.y, s_acc[9 + 2 * q]);
            f = __half22float2(hA1[q]);
            s_acc[2 * q] = fmaf(c1, f.x, s_acc[2 * q]);
            s_acc[2 * q + 1] = fmaf(c1, f.y, s_acc[2 * q + 1]);
            f = __half22float2(hB1[q]);
            s_acc[8 + 2 * q] = fmaf(c1, f.x, s_acc[8 + 2 * q]);
            s_acc[9 + 2 * q] = fmaf(c1, f.y, s_acc[9 + 2 * q]);
            f = __half22float2(hA2[q]);
            s_acc[2 * q] = fmaf(c2, f.x, s_acc[2 * q]);
            s_acc[2 * q + 1] = fmaf(c2, f.y, s_acc[2 * q + 1]);
            f = __half22float2(hB2[q]);
            s_acc[8 + 2 * q] = fmaf(c2, f.x, s_acc[8 + 2 * q]);
            s_acc[9 + 2 * q] = fmaf(c2, f.y, s_acc[9 + 2 * q]);
        }

        const int kn = k + 3;
        if (kn < nsup) {  // refill slot s (its readers just finished)
            RISSUE(jbeg + 3 * kn, s);
            RISSUE(jbeg + 3 * kn + 1, s + 1);
            RISSUE(jbeg + 3 * kn + 2, s + 2);
        }
        CP_COMMIT();
        s += 3;
        if (s == 9) s = 0;
    }
#undef RISSUE

    if (act) {
        float* sp = ((pass == 1) ? g_s1 : g_s2) + (b * NN + n) * OD;
#pragma unroll
        for (int o = 0; o < OD; o++) atomicAdd(sp + o, s_acc[o]);
    }
}

// ─────────────────── Final: v2 = squash(s2) -> output ───────────────────────
__global__ void k_squash_out(float* __restrict__ out) {
    int t = threadIdx.x;
    if (t >= BB * NN) return;
    const float4* sp = (const float4*)(g_s2 + t * OD);
    float4 a = sp[0], b4 = sp[1], c4 = sp[2], d4 = sp[3];
    float s[OD] = {a.x, a.y, a.z, a.w, b4.x, b4.y, b4.z, b4.w,
                   c4.x, c4.y, c4.z, c4.w, d4.x, d4.y, d4.z, d4.w};
    float sc = squash_scale(s);
    float4* op = (float4*)(out + t * OD);
    op[0] = make_float4(sc * s[0], sc * s[1], sc * s[2], sc * s[3]);
    op[1] = make_float4(sc * s[4], sc * s[5], sc * s[6], sc * s[7]);
    op[2] = make_float4(sc * s[8], sc * s[9], sc * s[10], sc * s[11]);
    op[3] = make_float4(sc * s[12], sc * s[13], sc * s[14], sc * s[15]);
}

extern "C" void kernel_launch(void* const* d_in, const int* in_sizes, int n_in,
                              void* d_out, int out_size) {
    const float* x = (const float*)d_in[0];  // [64, 6912, 16]
    const float* W = (const float*)d_in[1];  // [10, 6912, 16, 16]
    float* out = (float*)d_out;              // [64, 10, 16]

    cudaFuncSetAttribute(k_uhat, cudaFuncAttributeMaxDynamicSharedMemorySize,
                         UHAT_SMEM);

    k_xt<<<IC / JT, 256>>>(x);               // x -> fp16 [j][i][b]; zero s bufs
    k_uhat<<<IC / JB, NTH, UHAT_SMEM>>>(W);  // u_hat (fp16) + fused s0
    k_route<<<RT_BLOCKS, RT_TH>>>(1);        // squash(s0); emit s1
    k_route<<<RT_BLOCKS, RT_TH>>>(2);        // squash(s0)+squash(s1); emit s2
    k_squash_out<<<1, 640>>>(out);           // v2 -> output
}